// round 6
// baseline (speedup 1.0000x reference)
#include <cuda_runtime.h>
#include <cstdint>

// Problem constants
#define BATCH 20
#define CHN   60
#define HH    264
#define WW    264
#define PLANE (HH*WW)            // 69696

// Conv tiling: 132x2 tile, 264 threads, 2 CTAs/SM
#define TW    132
#define TH    2
#define OCT   5
#define OCG   12
#define PX    12
#define PXG   22                 // 2 rows * 11 col-segments
#define THREADS (OCG*PXG)        // 264
#define SXSTRIDE 136
#define TILE_ELEMS ((TH+2)*(TW+2))   // 536
#define FELEMS 1080

typedef unsigned long long ull;

// Scratch (device globals: no allocation allowed)
__device__ float g_gap[BATCH*CHN*9];
__device__ float g_fbuf[3*20*20*9];
__device__ float g_F2[60*60*9*2];    // [cin][oc][k][dup2]

__device__ __forceinline__ void unpack2(ull v, float& lo, float& hi) {
    asm("mov.b64 {%0, %1}, %2;" : "=f"(lo), "=f"(hi) : "l"(v));
}
__device__ __forceinline__ ull ffma2(ull a, ull b, ull c) {
    ull d;
    asm("fma.rn.f32x2 %0, %1, %2, %3;" : "=l"(d) : "l"(a), "l"(b), "l"(c));
    return d;
}

// ---------------- Kernel 1: 3x3 adaptive avg pool ----------------
__global__ void gap_kernel(const float* __restrict__ x) {
    const int bc = blockIdx.x;
    const float* p = x + (size_t)bc * PLANE;
    float s[9];
#pragma unroll
    for (int r = 0; r < 9; ++r) s[r] = 0.f;
    for (int i = threadIdx.x; i < PLANE; i += blockDim.x) {
        int h = i / WW, w = i - h * WW;
        int r = (h / 88) * 3 + (w / 88);
        s[r] += p[i];
    }
    __shared__ float red[9 * 8];
    const unsigned lane = threadIdx.x & 31u, warp = threadIdx.x >> 5;
#pragma unroll
    for (int r = 0; r < 9; ++r) {
        float v = s[r];
#pragma unroll
        for (int off = 16; off > 0; off >>= 1) v += __shfl_down_sync(0xffffffffu, v, off);
        if (lane == 0) red[r * 8 + warp] = v;
    }
    __syncthreads();
    if (threadIdx.x < 9) {
        float v = 0.f;
#pragma unroll
        for (int w = 0; w < 8; ++w) v += red[threadIdx.x * 8 + w];
        g_gap[bc * 9 + threadIdx.x] = v * (1.0f / 7744.0f);
    }
}

// ---------------- Kernel 2a: dynamic filters ----------------
__global__ void filt1_kernel(const float* __restrict__ w1, const float* __restrict__ b1,
                             const float* __restrict__ w2, const float* __restrict__ b2,
                             const float* __restrict__ w3, const float* __restrict__ b3,
                             const float* __restrict__ p1, const float* __restrict__ p2,
                             const float* __restrict__ p3) {
    int idx = blockIdx.x * blockDim.x + threadIdx.x;
    if (idx >= 3 * 20 * 20 * 9) return;
    int k = idx % 9;
    int i = (idx / 9) % 20;
    int j = (idx / 180) % 20;
    int g = idx / 3600;
    const float* w = (g == 0) ? w1 : (g == 1) ? w2 : w3;
    const float* bb = (g == 0) ? b1 : (g == 1) ? b2 : b3;
    const float para = (g == 0) ? p1[0] : (g == 1) ? p2[0] : p3[0];
    float acc = bb[i];
    const float* gp = g_gap + (j * 60) * 9 + k;
    const float* wr = w + i * 60;
#pragma unroll 10
    for (int c = 0; c < 60; ++c) acc += gp[c * 9] * wr[c];
    g_fbuf[idx] = tanhf(para * acc);
}

// ---------------- Kernel 2b: effective filters ----------------
__global__ void filt2_kernel(const float* __restrict__ w_out) {
    int idx = blockIdx.x * blockDim.x + threadIdx.x;
    if (idx >= 60 * 60 * 9) return;
    int k = idx % 9;
    int cin = (idx / 9) % 60;
    int oc = idx / 540;
    int g = cin / 20, i = cin % 20;
    float s = 0.f;
#pragma unroll
    for (int j = 0; j < 20; ++j)
        s += w_out[oc * 60 + g * 20 + j] * g_fbuf[((g * 20 + j) * 20 + i) * 9 + k];
    float* dst = g_F2 + cin * 1080 + (oc * 9 + k) * 2;
    dst[0] = s;
    dst[1] = s;
}

// ---------------- Kernel 3: fused conv, pipelined, dual-copy smem ----------------
__global__ void __launch_bounds__(THREADS, 2)
conv_kernel(const float* __restrict__ x, const float* __restrict__ b_out,
            float* __restrict__ out) {
    const int tx0 = blockIdx.x * TW;
    const int ty0 = blockIdx.y * TH;
    const int b   = blockIdx.z;
    const int tid = threadIdx.x;
    const int ocg = tid / PXG;                 // 0..11
    const int pxg = tid % PXG;                 // 0..21
    const int prow = pxg / 11;                 // 0..1
    const int pcol = (pxg % 11) * PX;          // 0..120

    // dual copies: s_x1[r][c] == s_x0[r][c+1]
    __shared__ __align__(16) float s_x0[2][(TH + 2) * SXSTRIDE];
    __shared__ __align__(16) float s_x1[2][(TH + 2) * SXSTRIDE];
    __shared__ __align__(16) float s_F[2][FELEMS];

    // ---- precompute x-tile load slots (3 slots; slot2 only for tid<8) ----
    int xoff[3], xd[3];    // gmem offset, smem dest (row*SXSTRIDE+c)
    bool xp_ok[3], xw_ok[3], xs1_ok[3];
#pragma unroll
    for (int s = 0; s < 3; ++s) {
        int i = tid + s * THREADS;
        bool inr = i < TILE_ELEMS;
        int r = i / (TW + 2), c = i - r * (TW + 2);
        int gy = ty0 - 1 + r, gx = tx0 - 1 + c;
        xw_ok[s] = inr;
        xp_ok[s] = inr && ((unsigned)gy < (unsigned)HH) && ((unsigned)gx < (unsigned)WW);
        xoff[s] = xp_ok[s] ? (gy * WW + gx) : 0;
        xd[s] = inr ? (r * SXSTRIDE + c) : 0;
        xs1_ok[s] = inr && (c > 0);            // write to shifted copy at c-1
    }
    // ---- F load slots (5 slots; slot4 only for tid<24) ----
    int fidx[5]; bool f_ok[5];
#pragma unroll
    for (int s = 0; s < 5; ++s) {
        int i = tid + s * THREADS;
        f_ok[s] = i < FELEMS;
        fidx[s] = f_ok[s] ? i : 0;
    }

    ull acc[OCT][PX / 2];
#pragma unroll
    for (int o = 0; o < OCT; ++o)
#pragma unroll
        for (int j = 0; j < PX / 2; ++j) acc[o][j] = 0ull;

    const float* xp = x + ((size_t)(b * CHN)) * PLANE;
    const float* Fp = g_F2;

    // ---- prologue: load cin=0 into buffer 0 ----
    {
        float xv[3], fv[5];
#pragma unroll
        for (int s = 0; s < 3; ++s) xv[s] = xp_ok[s] ? __ldg(xp + xoff[s]) : 0.f;
#pragma unroll
        for (int s = 0; s < 5; ++s) fv[s] = f_ok[s] ? __ldg(Fp + fidx[s]) : 0.f;
#pragma unroll
        for (int s = 0; s < 3; ++s) {
            if (xw_ok[s])  s_x0[0][xd[s]] = xv[s];
            if (xs1_ok[s]) s_x1[0][xd[s] - 1] = xv[s];
        }
#pragma unroll
        for (int s = 0; s < 5; ++s) if (f_ok[s]) s_F[0][fidx[s]] = fv[s];
    }
    __syncthreads();

#pragma unroll 2
    for (int cin = 0; cin < CHN; ++cin) {
        const int cur = cin & 1;
        const int nxt = cur ^ 1;

        // ---- prefetch cin+1 into registers ----
        float nxv[3] = {0.f, 0.f, 0.f}, nfv[5] = {0.f, 0.f, 0.f, 0.f, 0.f};
        const bool more = (cin + 1) < CHN;
        if (more) {
            const float* xq = xp + PLANE;
            const float* Fq = Fp + FELEMS;
#pragma unroll
            for (int s = 0; s < 3; ++s) if (xp_ok[s]) nxv[s] = __ldg(xq + xoff[s]);
#pragma unroll
            for (int s = 0; s < 5; ++s) if (f_ok[s]) nfv[s] = __ldg(Fq + fidx[s]);
        }

        // ---- compute on current buffers: aligned b64 pair loads, no packing ----
#pragma unroll
        for (int rr = 0; rr < 3; ++rr) {
            const ull* r0 = reinterpret_cast<const ull*>(&s_x0[cur][(prow + rr) * SXSTRIDE]) + (pcol >> 1);
            const ull* r1 = reinterpret_cast<const ull*>(&s_x1[cur][(prow + rr) * SXSTRIDE]) + (pcol >> 1);
            ull e[7], od[6];
#pragma unroll
            for (int j = 0; j < 7; ++j) e[j] = r0[j];    // pairs (2j, 2j+1)
#pragma unroll
            for (int j = 0; j < 6; ++j) od[j] = r1[j];   // pairs (2j+1, 2j+2)

#pragma unroll
            for (int o = 0; o < OCT; ++o) {
                const ull* frow = reinterpret_cast<const ull*>(
                    &s_F[cur][((ocg * OCT + o) * 9 + rr * 3) * 2]);
                ull f0 = frow[0], f1 = frow[1], f2 = frow[2];
#pragma unroll
                for (int j = 0; j < PX / 2; ++j) {
                    acc[o][j] = ffma2(e[j],     f0, acc[o][j]);
                    acc[o][j] = ffma2(od[j],    f1, acc[o][j]);
                    acc[o][j] = ffma2(e[j + 1], f2, acc[o][j]);
                }
            }
        }

        // ---- stage prefetched data into the other buffer ----
        if (more) {
#pragma unroll
            for (int s = 0; s < 3; ++s) {
                if (xw_ok[s])  s_x0[nxt][xd[s]] = nxv[s];
                if (xs1_ok[s]) s_x1[nxt][xd[s] - 1] = nxv[s];
            }
#pragma unroll
            for (int s = 0; s < 5; ++s) if (f_ok[s]) s_F[nxt][fidx[s]] = nfv[s];
            xp += PLANE;
            Fp += FELEMS;
        }
        __syncthreads();
    }

    // ---- epilogue ----
    const int h = ty0 + prow;
    const int w0 = tx0 + pcol;
#pragma unroll
    for (int o = 0; o < OCT; ++o) {
        const int oc = ocg * OCT + o;
        const float bo = b_out[oc];
        float v[12];
#pragma unroll
        for (int j = 0; j < PX / 2; ++j) {
            float lo, hi;
            unpack2(acc[o][j], lo, hi);
            v[2 * j] = lo + bo;
            v[2 * j + 1] = hi + bo;
        }
        float* op = out + (((size_t)(b * CHN + oc)) * HH + h) * WW + w0;
        reinterpret_cast<float4*>(op)[0] = make_float4(v[0], v[1], v[2], v[3]);
        reinterpret_cast<float4*>(op)[1] = make_float4(v[4], v[5], v[6], v[7]);
        reinterpret_cast<float4*>(op)[2] = make_float4(v[8], v[9], v[10], v[11]);
    }
}

// ---------------- launch ----------------
extern "C" void kernel_launch(void* const* d_in, const int* in_sizes, int n_in,
                              void* d_out, int out_size) {
    const float* x     = (const float*)d_in[0];
    const float* w1    = (const float*)d_in[1];
    const float* b1    = (const float*)d_in[2];
    const float* w2    = (const float*)d_in[3];
    const float* b2    = (const float*)d_in[4];
    const float* w3    = (const float*)d_in[5];
    const float* b3    = (const float*)d_in[6];
    const float* p1    = (const float*)d_in[7];
    const float* p2    = (const float*)d_in[8];
    const float* p3    = (const float*)d_in[9];
    const float* w_out = (const float*)d_in[10];
    const float* b_out = (const float*)d_in[11];
    float* out = (float*)d_out;

    gap_kernel<<<BATCH * CHN, 256>>>(x);
    filt1_kernel<<<(10800 + 255) / 256, 256>>>(w1, b1, w2, b2, w3, b3, p1, p2, p3);
    filt2_kernel<<<(32400 + 255) / 256, 256>>>(w_out);
    dim3 grid(WW / TW, HH / TH, BATCH);   // (2, 132, 20)
    conv_kernel<<<grid, THREADS>>>(x, b_out, out);
}